// round 14
// baseline (speedup 1.0000x reference)
#include <cuda_runtime.h>

#define N_NODES 10000
#define N_PAD   10048
#define N_EDGES 160000
#define HID     512
#define EPS     1e-5f

// ---------------- scratch (static __device__, allowed) ----------------
__device__ float g_dis[N_NODES];
__device__ int   g_cnt[N_NODES];
__device__ int   g_rowptr[N_NODES + 1];
__device__ int   g_cur[N_NODES];
__device__ int   g_src[N_EDGES];
__device__ float g_nrm[N_EDGES];
__device__ float g_agg[N_PAD * HID];
__device__ float g_h  [N_PAD * HID];
__device__ float g_A  [N_PAD * 1024];
__device__ float g_B  [N_PAD * 1024];
__device__ unsigned g_W1t[1024 * 512];   // mw1 pre-converted to tf32
__device__ int   g_is64;

__device__ __forceinline__ float warp_sum(float v) {
#pragma unroll
    for (int o = 16; o > 0; o >>= 1) v += __shfl_xor_sync(0xffffffffu, v, o);
    return v;
}

// ---- packed fp32x2 FMA ----
#define FMA2(d, a, b) asm("fma.rn.f32x2 %0, %1, %2, %0;" : "+l"(d) : "l"(a), "l"(b))
__device__ __forceinline__ unsigned long long bcast2(float a) {
    unsigned long long r;
    asm("mov.b64 %0, {%1, %1};" : "=l"(r) : "f"(a));
    return r;
}
__device__ __forceinline__ void unpack2(unsigned long long d, float& lo, float& hi) {
    asm("mov.b64 {%0, %1}, %2;" : "=f"(lo), "=f"(hi) : "l"(d));
}

// ---- tf32 helpers ----
__device__ __forceinline__ unsigned tf32cvt(float f) {
    unsigned u; asm("cvt.rna.tf32.f32 %0, %1;" : "=r"(u) : "f"(f)); return u;
}
__device__ __forceinline__ void mma_tf32(float* c,
    unsigned a0, unsigned a1, unsigned a2, unsigned a3,
    unsigned b0, unsigned b1)
{
    asm volatile(
        "mma.sync.aligned.m16n8k8.row.col.f32.tf32.tf32.f32 "
        "{%0,%1,%2,%3}, {%4,%5,%6,%7}, {%8,%9}, {%0,%1,%2,%3};"
        : "+f"(c[0]), "+f"(c[1]), "+f"(c[2]), "+f"(c[3])
        : "r"(a0), "r"(a1), "r"(a2), "r"(a3), "r"(b0), "r"(b1));
}

// ---- cp.async helpers ----
__device__ __forceinline__ void cpasync16(void* smem_dst, const void* gsrc) {
    unsigned saddr = (unsigned)__cvta_generic_to_shared(smem_dst);
    asm volatile("cp.async.cg.shared.global [%0], [%1], 16;"
                 :: "r"(saddr), "l"(gsrc));
}
#define CP_COMMIT() asm volatile("cp.async.commit_group;" ::: "memory")
#define CP_WAIT0()  asm volatile("cp.async.wait_group 0;" ::: "memory")

// edge_index may be int32 (JAX default) or int64; g_is64 selects.
__device__ __forceinline__ int eidx(const void* __restrict__ ei, int pos) {
    return g_is64 ? (int)((const long long*)ei)[pos] : ((const int*)ei)[pos];
}

// ---------------- dtype detection ----------------
__global__ void k_detect(const int* __restrict__ ei32) {
    if (threadIdx.x == 0) {
        int all0 = 1;
        for (int i = 0; i < 1000; i++)
            if (ei32[2 * i + 1] != 0) { all0 = 0; break; }
        g_is64 = all0;
    }
}

// ---------------- W1 pre-convert to tf32 ----------------
__global__ void k_w1cvt(const float* __restrict__ W1) {
    int i = (blockIdx.x * blockDim.x + threadIdx.x) * 4;
    float4 w4 = *(const float4*)&W1[i];
    uint4 o;
    o.x = tf32cvt(w4.x); o.y = tf32cvt(w4.y);
    o.z = tf32cvt(w4.z); o.w = tf32cvt(w4.w);
    *(uint4*)&g_W1t[i] = o;
}

// ---------------- CSR build ----------------
__global__ void k_cnt_zero() {
    int i = blockIdx.x * blockDim.x + threadIdx.x;
    if (i < N_NODES) g_cnt[i] = 0;
}
__global__ void k_cnt_acc(const void* __restrict__ ei) {
    int e = blockIdx.x * blockDim.x + threadIdx.x;
    if (e < N_EDGES) atomicAdd(&g_cnt[eidx(ei, N_EDGES + e)], 1);
}
#define SCAN_T 1024
#define SCAN_C 10
__global__ void __launch_bounds__(SCAN_T) k_scan() {
    __shared__ int part[SCAN_T];
    int t = threadIdx.x;
    int base = t * SCAN_C;
    int loc[SCAN_C];
    int s = 0;
#pragma unroll
    for (int i = 0; i < SCAN_C; i++) {
        int n = base + i;
        int c = (n < N_NODES) ? g_cnt[n] : 0;
        loc[i] = s; s += c;
    }
    part[t] = s;
    __syncthreads();
    for (int off = 1; off < SCAN_T; off <<= 1) {
        int v = (t >= off) ? part[t - off] : 0;
        __syncthreads();
        part[t] += v;
        __syncthreads();
    }
    int pre = (t > 0) ? part[t - 1] : 0;
#pragma unroll
    for (int i = 0; i < SCAN_C; i++) {
        int n = base + i;
        if (n < N_NODES) {
            int p = pre + loc[i];
            g_rowptr[n] = p;
            g_cur[n]    = p;
            g_dis[n]    = rsqrtf((float)g_cnt[n] + 1.0f);  // +1 self-loop
        }
    }
    if (t == SCAN_T - 1) g_rowptr[N_NODES] = part[t];
}
__global__ void k_fill(const void* __restrict__ ei) {
    int e = blockIdx.x * blockDim.x + threadIdx.x;
    if (e >= N_EDGES) return;
    int r = eidx(ei, e);
    int c = eidx(ei, N_EDGES + e);
    int p = atomicAdd(&g_cur[c], 1);
    g_src[p] = r;
    g_nrm[p] = g_dis[r] * g_dis[c];
}

// ---------------- aggregation: pure gather via CSR (no atomics) ----------------
__global__ void __launch_bounds__(128) k_gather512(const float* __restrict__ h,
                                                   float* __restrict__ agg) {
    int v = blockIdx.x;
    int t = threadIdx.x;
    int b = g_rowptr[v], e = g_rowptr[v + 1];
    float s = g_dis[v]; s *= s;
    float4 hv = *(const float4*)&h[(size_t)v * 512 + t * 4];
    float4 acc;
    acc.x = s * hv.x; acc.y = s * hv.y; acc.z = s * hv.z; acc.w = s * hv.w;
    for (int j = b; j < e; j++) {
        int   src = g_src[j];
        float nr  = g_nrm[j];
        float4 x = *(const float4*)&h[(size_t)src * 512 + t * 4];
        acc.x += nr * x.x; acc.y += nr * x.y;
        acc.z += nr * x.z; acc.w += nr * x.w;
    }
    *(float4*)&agg[(size_t)v * 512 + t * 4] = acc;
}
__global__ void __launch_bounds__(128) k_gather128(const float* __restrict__ h,
                                                   float* __restrict__ agg) {
    int v = blockIdx.x;
    int t = threadIdx.x;
    int b = g_rowptr[v], e = g_rowptr[v + 1];
    float s = g_dis[v]; s *= s;
    float acc = s * h[(size_t)v * 128 + t];
    for (int j = b; j < e; j++)
        acc += g_nrm[j] * h[(size_t)g_src[j] * 128 + t];
    agg[(size_t)v * 128 + t] = acc;
}

// ---------------- GCN GEMM + bias + ReLU + LayerNorm ----------------
__global__ void __launch_bounds__(256) k_gcn(
    const float* __restrict__ A, const float* __restrict__ W,
    const float* __restrict__ bias, const float* __restrict__ gam,
    const float* __restrict__ bet, float* __restrict__ out, int K)
{
    __shared__ float sA[16][16];
    __shared__ float sW[16][512];
    __shared__ float rsum[16][4], rsq[16][4];
    int t = threadIdx.x;
    int tx = t & 127, ty = t >> 7;
    int row0 = blockIdx.x * 16;
    unsigned long long a64[8][2];
#pragma unroll
    for (int j = 0; j < 8; j++) { a64[j][0] = 0ull; a64[j][1] = 0ull; }

    for (int k0 = 0; k0 < K; k0 += 16) {
        sA[t >> 4][t & 15] = A[(row0 + (t >> 4)) * K + k0 + (t & 15)];
#pragma unroll
        for (int i = 0; i < 8; i++) {
            int idx = t + i * 256;
            int kk = idx >> 7, c4 = idx & 127;
            *(float4*)&sW[kk][c4 * 4] = *(const float4*)&W[(k0 + kk) * 512 + c4 * 4];
        }
        __syncthreads();
#pragma unroll
        for (int kk = 0; kk < 16; kk++) {
            ulonglong2 w2 = *(ulonglong2*)&sW[kk][tx * 4];
#pragma unroll
            for (int j = 0; j < 8; j++) {
                unsigned long long aa = bcast2(sA[ty + j * 2][kk]);
                FMA2(a64[j][0], aa, w2.x);
                FMA2(a64[j][1], aa, w2.y);
            }
        }
        __syncthreads();
    }

    float acc[8][4];
#pragma unroll
    for (int j = 0; j < 8; j++) {
        unpack2(a64[j][0], acc[j][0], acc[j][1]);
        unpack2(a64[j][1], acc[j][2], acc[j][3]);
    }

    float4 b4 = *(const float4*)&bias[tx * 4];
    int lane = t & 31, quarter = (t >> 5) & 3;
#pragma unroll
    for (int j = 0; j < 8; j++) {
        acc[j][0] = fmaxf(acc[j][0] + b4.x, 0.f);
        acc[j][1] = fmaxf(acc[j][1] + b4.y, 0.f);
        acc[j][2] = fmaxf(acc[j][2] + b4.z, 0.f);
        acc[j][3] = fmaxf(acc[j][3] + b4.w, 0.f);
        int r = ty + j * 2;
        float s = acc[j][0] + acc[j][1] + acc[j][2] + acc[j][3];
        float q = acc[j][0]*acc[j][0] + acc[j][1]*acc[j][1]
                + acc[j][2]*acc[j][2] + acc[j][3]*acc[j][3];
        s = warp_sum(s); q = warp_sum(q);
        if (lane == 0) { rsum[r][quarter] = s; rsq[r][quarter] = q; }
    }
    __syncthreads();
    float4 g4  = *(const float4*)&gam[tx * 4];
    float4 be4 = *(const float4*)&bet[tx * 4];
#pragma unroll
    for (int j = 0; j < 8; j++) {
        int r = ty + j * 2;
        float s = rsum[r][0] + rsum[r][1] + rsum[r][2] + rsum[r][3];
        float q = rsq[r][0]  + rsq[r][1]  + rsq[r][2]  + rsq[r][3];
        float mu  = s * (1.f / 512.f);
        float var = q * (1.f / 512.f) - mu * mu;
        float rs  = rsqrtf(var + EPS);
        float4 o;
        o.x = (acc[j][0] - mu) * rs * g4.x + be4.x;
        o.y = (acc[j][1] - mu) * rs * g4.y + be4.y;
        o.z = (acc[j][2] - mu) * rs * g4.z + be4.z;
        o.w = (acc[j][3] - mu) * rs * g4.w + be4.w;
        *(float4*)&out[(row0 + r) * 512 + tx * 4] = o;
    }
}

// ---------------- tiled GEMM: C[N_PAD,1024] = Ain[N_PAD,512] @ W[512,1024] ----------------
__global__ void __launch_bounds__(256) k_gemm64(
    const float* __restrict__ Ain, const float* __restrict__ W, float* __restrict__ C)
{
    __shared__ float sA[64][20];
    __shared__ float sB[16][64];
    int t = threadIdx.x;
    int tx = t & 15, ty = t >> 4;
    int c0 = blockIdx.x * 64, r0 = blockIdx.y * 64;
    unsigned long long a64[4][2];
#pragma unroll
    for (int i = 0; i < 4; i++) { a64[i][0] = 0ull; a64[i][1] = 0ull; }

    for (int k0 = 0; k0 < 512; k0 += 16) {
        {
            int r = t >> 2, q = t & 3;
            *(float4*)&sA[r][q * 4] = *(const float4*)&Ain[(r0 + r) * 512 + k0 + q * 4];
        }
        {
            int kk = t >> 4, c4 = t & 15;
            *(float4*)&sB[kk][c4 * 4] = *(const float4*)&W[(size_t)(k0 + kk) * 1024 + c0 + c4 * 4];
        }
        __syncthreads();
#pragma unroll
        for (int kk = 0; kk < 16; kk++) {
            ulonglong2 b2 = *(ulonglong2*)&sB[kk][tx * 4];
#pragma unroll
            for (int i = 0; i < 4; i++) {
                unsigned long long aa = bcast2(sA[ty * 4 + i][kk]);
                FMA2(a64[i][0], aa, b2.x);
                FMA2(a64[i][1], aa, b2.y);
            }
        }
        __syncthreads();
    }
#pragma unroll
    for (int i = 0; i < 4; i++) {
        float4 o;
        unpack2(a64[i][0], o.x, o.y);
        unpack2(a64[i][1], o.z, o.w);
        *(float4*)&C[(size_t)(r0 + ty * 4 + i) * 1024 + c0 + tx * 4] = o;
    }
}

// ---------------- fused edge MLP (stages 1+2, tensor cores, double-buffered) ----------------
// dynamic smem layout (words):
//   Wbuf: 2 * 16 * 520      (tf32 W chunks, double-buffered)
//   Zbuf: 2 * 64 * 20       (tf32 Z chunks, double-buffered)
//   ps, pq, pd: 64*4 each   (epilogue partials)
//   sS, sD: 64 each; sMu, sRs: 64 each
#define WSTR   520
#define WBUFW  (16 * WSTR)
#define ZBUFW  (64 * 20)
#define E12_SMEM_WORDS (2*WBUFW + 2*ZBUFW + 3*256 + 2*64 + 2*64)
#define E12_SMEM_BYTES (E12_SMEM_WORDS * 4)

__global__ void __launch_bounds__(512, 1) k_edge12(
    const void* __restrict__ ei,
    const float* __restrict__ mb0, const float* __restrict__ mg0,
    const float* __restrict__ mbt0,
    const float* __restrict__ mb1,
    const float* __restrict__ g, const float* __restrict__ bt,
    const float* __restrict__ mw2, const float* __restrict__ mb2,
    float* __restrict__ out)
{
    extern __shared__ unsigned dyn[];
    unsigned* Wbuf = dyn;                    // [2][16][520]
    unsigned* Zbuf = dyn + 2 * WBUFW;        // [2][64][20]
    float* ps  = (float*)(Zbuf + 2 * ZBUFW); // [64][4]
    float* pq  = ps + 256;
    float* pd  = pq + 256;
    int*   sS  = (int*)(pd + 256);
    int*   sD  = sS + 64;
    float* sMu = (float*)(sD + 64);
    float* sRs = sMu + 64;

    int t = threadIdx.x;
    int w = t >> 5, lane = t & 31;
    int gq = lane >> 2, tig = lane & 3;
    int row_half = w & 3, s = w >> 2;
    int lr0 = row_half * 16;
    int c0s = s * 128;
    int e0 = blockIdx.x * 64;

    if (t < 64) {
        sS[t] = eidx(ei, e0 + t);
        sD[t] = eidx(ei, N_EDGES + e0 + t);
    }
    __syncthreads();

    // ---- pass 1: LN stats (each warp: 4 rows) ----
#pragma unroll
    for (int rr = 0; rr < 4; rr++) {
        int r = w * 4 + rr;
        const float* pa = &g_A[(size_t)sS[r] * 1024];
        const float* pb = &g_B[(size_t)sD[r] * 1024];
        float sm = 0.f, sq = 0.f;
#pragma unroll
        for (int i = 0; i < 8; i++) {
            int c = i * 128 + lane * 4;
            float4 a = *(const float4*)&pa[c];
            float4 b = *(const float4*)&pb[c];
            float4 m = *(const float4*)&mb0[c];
            float v0 = a.x + b.x + m.x, v1 = a.y + b.y + m.y;
            float v2 = a.z + b.z + m.z, v3 = a.w + b.w + m.w;
            sm += v0 + v1 + v2 + v3;
            sq += v0*v0 + v1*v1 + v2*v2 + v3*v3;
        }
        sm = warp_sum(sm); sq = warp_sum(sq);
        if (lane == 0) {
            float mu = sm * (1.f / 1024.f);
            float var = sq * (1.f / 1024.f) - mu * mu;
            sMu[r] = mu;
            sRs[r] = rsqrtf(var + EPS);
        }
    }
    __syncthreads();

    float acc[16][4];
#pragma unroll
    for (int i = 0; i < 16; i++) { acc[i][0]=0.f; acc[i][1]=0.f; acc[i][2]=0.f; acc[i][3]=0.f; }

    int zrow = t >> 3, zkk = (t & 7) * 2;
    const float* zpa = &g_A[(size_t)sS[zrow] * 1024];
    const float* zpb = &g_B[(size_t)sD[zrow] * 1024];
    float zmu = sMu[zrow], zrs = sRs[zrow];

    // ---- prologue: stage chunk 0 into buffer 0 ----
    {
        float2 a2 = *(const float2*)&zpa[zkk];
        float2 b2 = *(const float2*)&zpb[zkk];
        float2 m2 = *(const float2*)&mb0[zkk];
        float2 gg = *(const float2*)&mg0[zkk];
        float2 bb = *(const float2*)&mbt0[zkk];
        float z0 = fmaxf((a2.x + b2.x + m2.x - zmu) * zrs * gg.x + bb.x, 0.f);
        float z1 = fmaxf((a2.y + b2.y + m2.y - zmu) * zrs * gg.y + bb.y, 0.f);
        Zbuf[zrow * 20 + zkk]     = tf32cvt(z0);
        Zbuf[zrow * 20 + zkk + 1] = tf32cvt(z1);
#pragma unroll
        for (int i = 0; i < 4; i++) {
            int vi = t + i * 512;
            int kk = vi >> 7, c4 = vi & 127;
            cpasync16(&Wbuf[kk * WSTR + c4 * 4], &g_W1t[(size_t)kk * 512 + c4 * 4]);
        }
        CP_COMMIT(); CP_WAIT0();
    }
    __syncthreads();

    // ---- main k-loop (double-buffered, 1 sync/iter) ----
    for (int k0 = 0; k0 < 1024; k0 += 16) {
        int it  = k0 >> 4;
        int cur = it & 1, nxt = cur ^ 1;
        bool hn = (k0 + 16 < 1024);
        float2 a2n, b2n;
        if (hn) {
            int c = k0 + 16 + zkk;
            a2n = *(const float2*)&zpa[c];
            b2n = *(const float2*)&zpb[c];
#pragma unroll
            for (int i = 0; i < 4; i++) {
                int vi = t + i * 512;
                int kk = vi >> 7, c4 = vi & 127;
                cpasync16(&Wbuf[nxt * WBUFW + kk * WSTR + c4 * 4],
                          &g_W1t[(size_t)(k0 + 16 + kk) * 512 + c4 * 4]);
            }
            CP_COMMIT();
        }
        // mma on current buffers (LDG + cp.async in flight behind it)
        const unsigned* Wc = &Wbuf[cur * WBUFW];
        const unsigned* Zc = &Zbuf[cur * ZBUFW];
#pragma unroll
        for (int k8 = 0; k8 < 16; k8 += 8) {
            unsigned a0 = Zc[(lr0 + gq     ) * 20 + k8 + tig];
            unsigned a1 = Zc[(lr0 + gq +  8) * 20 + k8 + tig];
            unsigned a2 = Zc[(lr0 + gq     ) * 20 + k8 + tig + 4];
            unsigned a3 = Zc[(lr0 + gq +  8) * 20 + k8 + tig + 4];
#pragma unroll
            for (int i = 0; i < 16; i++) {
                unsigned b0 = Wc[(k8 + tig    ) * WSTR + c0s + i * 8 + gq];
                unsigned b1 = Wc[(k8 + tig + 4) * WSTR + c0s + i * 8 + gq];
                mma_tf32(acc[i], a0, a1, a2, a3, b0, b1);
            }
        }
        if (hn) {
            int c = k0 + 16 + zkk;
            float2 m2 = *(const float2*)&mb0[c];
            float2 gg = *(const float2*)&mg0[c];
            float2 bb = *(const float2*)&mbt0[c];
            float z0 = fmaxf((a2n.x + b2n.x + m2.x - zmu) * zrs * gg.x + bb.x, 0.f);
            float z1 = fmaxf((a2n.y + b2n.y + m2.y - zmu) * zrs * gg.y + bb.y, 0.f);
            Zbuf[nxt * ZBUFW + zrow * 20 + zkk]     = tf32cvt(z0);
            Zbuf[nxt * ZBUFW + zrow * 20 + zkk + 1] = tf32cvt(z1);
            CP_WAIT0();
        }
        __syncthreads();
    }

    int rA = lr0 + gq, rB = rA + 8;

    float sA = 0.f, qA = 0.f, sB = 0.f, qB = 0.f;
#pragma unroll
    for (int i = 0; i < 16; i++) {
        int col = c0s + i * 8 + 2 * tig;
        float2 b2 = *(const float2*)&mb1[col];
        acc[i][0] += b2.x; acc[i][1] += b2.y;
        acc[i][2] += b2.x; acc[i][3] += b2.y;
        sA += acc[i][0] + acc[i][1];
        qA += acc[i][0]*acc[i][0] + acc[i][1]*acc[i][1];
        sB += acc[i][2] + acc[i][3];
        qB += acc[i][2]*acc[i][2] + acc[i][3]*acc[i][3];
    }
#pragma unroll
    for (int o = 1; o <= 2; o <<= 1) {
        sA += __shfl_xor_sync(0xffffffffu, sA, o);
        qA += __shfl_xor_sync(0xffffffffu, qA, o);
        sB += __shfl_xor_sync(0xffffffffu, sB, o);
        qB += __shfl_xor_sync(0xffffffffu, qB, o);
    }
    if (tig == 0) { ps[rA*4+s] = sA; pq[rA*4+s] = qA; ps[rB*4+s] = sB; pq[rB*4+s] = qB; }
    __syncthreads();

    float SA = ps[rA*4+0] + ps[rA*4+1] + ps[rA*4+2] + ps[rA*4+3];
    float QA = pq[rA*4+0] + pq[rA*4+1] + pq[rA*4+2] + pq[rA*4+3];
    float SB = ps[rB*4+0] + ps[rB*4+1] + ps[rB*4+2] + ps[rB*4+3];
    float QB = pq[rB*4+0] + pq[rB*4+1] + pq[rB*4+2] + pq[rB*4+3];
    float muA = SA * (1.f / 512.f);
    float rsA = rsqrtf(QA * (1.f / 512.f) - muA * muA + EPS);
    float muB = SB * (1.f / 512.f);
    float rsB = rsqrtf(QB * (1.f / 512.f) - muB * muB + EPS);

    float dA = 0.f, dB = 0.f;
#pragma unroll
    for (int i = 0; i < 16; i++) {
        int col = c0s + i * 8 + 2 * tig;
        float2 gm = *(const float2*)&g[col];
        float2 bb = *(const float2*)&bt[col];
        float2 w2 = *(const float2*)&mw2[col];
        dA += fmaxf((acc[i][0] - muA) * rsA * gm.x + bb.x, 0.f) * w2.x
            + fmaxf((acc[i][1] - muA) * rsA * gm.y + bb.y, 0.f) * w2.y;
        dB += fmaxf((acc[i][2] - muB) * rsB * gm.x + bb.x, 0.f) * w2.x
            + fmaxf((acc[i][3] - muB) * rsB * gm.y + bb.y, 0.f) * w2.y;
    }
#pragma unroll
    for (int o = 1; o <= 2; o <<= 1) {
        dA += __shfl_xor_sync(0xffffffffu, dA, o);
        dB += __shfl_xor_sync(0xffffffffu, dB, o);
    }
    if (tig == 0) { pd[rA*4+s] = dA; pd[rB*4+s] = dB; }
    __syncthreads();

    if (t < 64)
        out[e0 + t] = pd[t*4+0] + pd[t*4+1] + pd[t*4+2] + pd[t*4+3] + mb2[0];
}

// ---------------- launch ----------------
extern "C" void kernel_launch(void* const* d_in, const int* in_sizes, int n_in,
                              void* d_out, int out_size)
{
    const float* x    = (const float*)d_in[0];
    const void*  ei   = d_in[1];
    const float* w0   = (const float*)d_in[2];
    const float* b0   = (const float*)d_in[3];
    const float* ws   = (const float*)d_in[4];
    const float* bs   = (const float*)d_in[5];
    const float* lng  = (const float*)d_in[6];
    const float* lnb  = (const float*)d_in[7];
    const float* mw0  = (const float*)d_in[8];
    const float* mb0  = (const float*)d_in[9];
    const float* mg0  = (const float*)d_in[10];
    const float* mbt0 = (const float*)d_in[11];
    const float* mw1  = (const float*)d_in[12];
    const float* mb1  = (const float*)d_in[13];
    const float* mg1  = (const float*)d_in[14];
    const float* mbt1 = (const float*)d_in[15];
    const float* mw2  = (const float*)d_in[16];
    const float* mb2  = (const float*)d_in[17];
    float* out = (float*)d_out;

    float *p_agg, *p_h, *p_A, *p_B;
    cudaGetSymbolAddress((void**)&p_agg, g_agg);
    cudaGetSymbolAddress((void**)&p_h,   g_h);
    cudaGetSymbolAddress((void**)&p_A,   g_A);
    cudaGetSymbolAddress((void**)&p_B,   g_B);

    cudaFuncSetAttribute(k_edge12, cudaFuncAttributeMaxDynamicSharedMemorySize,
                         E12_SMEM_BYTES);

    // dtype detect + CSR build + W1 tf32 pre-convert
    k_detect<<<1, 32>>>((const int*)ei);
    k_cnt_zero<<<(N_NODES + 255) / 256, 256>>>();
    k_cnt_acc <<<(N_EDGES + 255) / 256, 256>>>(ei);
    k_scan<<<1, SCAN_T>>>();
    k_fill<<<(N_EDGES + 255) / 256, 256>>>(ei);
    k_w1cvt<<<512, 256>>>(mw1);

    // layer 0 (aggregate in 128-dim input space, then GEMM 128->512)
    k_gather128<<<N_NODES, 128>>>(x, p_agg);
    k_gcn<<<N_NODES / 16, 256>>>(p_agg, w0, b0, lng, lnb, p_h, 128);

    // layers 1..3
    for (int i = 1; i < 4; i++) {
        k_gather512<<<N_NODES, 128>>>(p_h, p_agg);
        k_gcn<<<N_NODES / 16, 256>>>(p_agg, ws + (size_t)(i - 1) * 512 * 512,
                                     bs + (i - 1) * 512, lng + i * 512, lnb + i * 512,
                                     p_h, 512);
    }

    // edge MLP first layer factored per-node: A = h @ mw0[:512], B = h @ mw0[512:]
    dim3 gAB(16, N_PAD / 64);
    k_gemm64<<<gAB, 256>>>(p_h, mw0, p_A);
    k_gemm64<<<gAB, 256>>>(p_h, mw0 + (size_t)512 * 1024, p_B);

    // fused: relu(LN(A[s]+B[t]+mb0)) @ mw1 -> LN -> relu -> dot(mw2) + mb2
    k_edge12<<<N_EDGES / 64, 512, E12_SMEM_BYTES>>>(ei, mb0, mg0, mbt0,
                                                    mb1, mg1, mbt1, mw2, mb2, out);
}

// round 15
// speedup vs baseline: 1.5388x; 1.5388x over previous
#include <cuda_runtime.h>

#define N_NODES 10000
#define N_PAD   10048
#define N_EDGES 160000
#define HID     512
#define EPS     1e-5f

// ---------------- scratch (static __device__, allowed) ----------------
__device__ float g_dis[N_NODES];
__device__ int   g_cnt[N_NODES];
__device__ int   g_rowptr[N_NODES + 1];
__device__ int   g_cur[N_NODES];
__device__ int   g_src[N_EDGES];
__device__ float g_nrm[N_EDGES];
__device__ float g_agg[N_PAD * HID];
__device__ float g_h  [N_PAD * HID];
__device__ float g_A  [N_PAD * 1024];
__device__ float g_B  [N_PAD * 1024];
__device__ unsigned g_W1t[1024 * 512];   // mw1 pre-converted to tf32
__device__ int   g_is64;

__device__ __forceinline__ float warp_sum(float v) {
#pragma unroll
    for (int o = 16; o > 0; o >>= 1) v += __shfl_xor_sync(0xffffffffu, v, o);
    return v;
}

// ---- packed fp32x2 FMA ----
#define FMA2(d, a, b) asm("fma.rn.f32x2 %0, %1, %2, %0;" : "+l"(d) : "l"(a), "l"(b))
__device__ __forceinline__ unsigned long long bcast2(float a) {
    unsigned long long r;
    asm("mov.b64 %0, {%1, %1};" : "=l"(r) : "f"(a));
    return r;
}
__device__ __forceinline__ void unpack2(unsigned long long d, float& lo, float& hi) {
    asm("mov.b64 {%0, %1}, %2;" : "=f"(lo), "=f"(hi) : "l"(d));
}

// ---- tf32 helpers ----
__device__ __forceinline__ unsigned tf32cvt(float f) {
    unsigned u; asm("cvt.rna.tf32.f32 %0, %1;" : "=r"(u) : "f"(f)); return u;
}
__device__ __forceinline__ void mma_tf32(float* c,
    unsigned a0, unsigned a1, unsigned a2, unsigned a3,
    unsigned b0, unsigned b1)
{
    asm volatile(
        "mma.sync.aligned.m16n8k8.row.col.f32.tf32.tf32.f32 "
        "{%0,%1,%2,%3}, {%4,%5,%6,%7}, {%8,%9}, {%0,%1,%2,%3};"
        : "+f"(c[0]), "+f"(c[1]), "+f"(c[2]), "+f"(c[3])
        : "r"(a0), "r"(a1), "r"(a2), "r"(a3), "r"(b0), "r"(b1));
}

// ---- cp.async helpers ----
__device__ __forceinline__ void cpasync16(void* smem_dst, const void* gsrc) {
    unsigned saddr = (unsigned)__cvta_generic_to_shared(smem_dst);
    asm volatile("cp.async.cg.shared.global [%0], [%1], 16;"
                 :: "r"(saddr), "l"(gsrc));
}
#define CP_COMMIT() asm volatile("cp.async.commit_group;" ::: "memory")
#define CP_WAIT0()  asm volatile("cp.async.wait_group 0;" ::: "memory")
#define CP_WAIT1()  asm volatile("cp.async.wait_group 1;" ::: "memory")

// edge_index may be int32 (JAX default) or int64; g_is64 selects.
__device__ __forceinline__ int eidx(const void* __restrict__ ei, int pos) {
    return g_is64 ? (int)((const long long*)ei)[pos] : ((const int*)ei)[pos];
}

// ---------------- dtype detection ----------------
__global__ void k_detect(const int* __restrict__ ei32) {
    if (threadIdx.x == 0) {
        int all0 = 1;
        for (int i = 0; i < 1000; i++)
            if (ei32[2 * i + 1] != 0) { all0 = 0; break; }
        g_is64 = all0;
    }
}

// ---------------- W1 pre-convert to tf32 ----------------
__global__ void k_w1cvt(const float* __restrict__ W1) {
    int i = (blockIdx.x * blockDim.x + threadIdx.x) * 4;
    float4 w4 = *(const float4*)&W1[i];
    uint4 o;
    o.x = tf32cvt(w4.x); o.y = tf32cvt(w4.y);
    o.z = tf32cvt(w4.z); o.w = tf32cvt(w4.w);
    *(uint4*)&g_W1t[i] = o;
}

// ---------------- CSR build ----------------
__global__ void k_cnt_zero() {
    int i = blockIdx.x * blockDim.x + threadIdx.x;
    if (i < N_NODES) g_cnt[i] = 0;
}
__global__ void k_cnt_acc(const void* __restrict__ ei) {
    int e = blockIdx.x * blockDim.x + threadIdx.x;
    if (e < N_EDGES) atomicAdd(&g_cnt[eidx(ei, N_EDGES + e)], 1);
}
#define SCAN_T 1024
#define SCAN_C 10
__global__ void __launch_bounds__(SCAN_T) k_scan() {
    __shared__ int part[SCAN_T];
    int t = threadIdx.x;
    int base = t * SCAN_C;
    int loc[SCAN_C];
    int s = 0;
#pragma unroll
    for (int i = 0; i < SCAN_C; i++) {
        int n = base + i;
        int c = (n < N_NODES) ? g_cnt[n] : 0;
        loc[i] = s; s += c;
    }
    part[t] = s;
    __syncthreads();
    for (int off = 1; off < SCAN_T; off <<= 1) {
        int v = (t >= off) ? part[t - off] : 0;
        __syncthreads();
        part[t] += v;
        __syncthreads();
    }
    int pre = (t > 0) ? part[t - 1] : 0;
#pragma unroll
    for (int i = 0; i < SCAN_C; i++) {
        int n = base + i;
        if (n < N_NODES) {
            int p = pre + loc[i];
            g_rowptr[n] = p;
            g_cur[n]    = p;
            g_dis[n]    = rsqrtf((float)g_cnt[n] + 1.0f);  // +1 self-loop
        }
    }
    if (t == SCAN_T - 1) g_rowptr[N_NODES] = part[t];
}
__global__ void k_fill(const void* __restrict__ ei) {
    int e = blockIdx.x * blockDim.x + threadIdx.x;
    if (e >= N_EDGES) return;
    int r = eidx(ei, e);
    int c = eidx(ei, N_EDGES + e);
    int p = atomicAdd(&g_cur[c], 1);
    g_src[p] = r;
    g_nrm[p] = g_dis[r] * g_dis[c];
}

// ---------------- aggregation: pure gather via CSR (no atomics) ----------------
__global__ void __launch_bounds__(128) k_gather512(const float* __restrict__ h,
                                                   float* __restrict__ agg) {
    int v = blockIdx.x;
    int t = threadIdx.x;
    int b = g_rowptr[v], e = g_rowptr[v + 1];
    float s = g_dis[v]; s *= s;
    float4 hv = *(const float4*)&h[(size_t)v * 512 + t * 4];
    float4 acc;
    acc.x = s * hv.x; acc.y = s * hv.y; acc.z = s * hv.z; acc.w = s * hv.w;
    for (int j = b; j < e; j++) {
        int   src = g_src[j];
        float nr  = g_nrm[j];
        float4 x = *(const float4*)&h[(size_t)src * 512 + t * 4];
        acc.x += nr * x.x; acc.y += nr * x.y;
        acc.z += nr * x.z; acc.w += nr * x.w;
    }
    *(float4*)&agg[(size_t)v * 512 + t * 4] = acc;
}
__global__ void __launch_bounds__(128) k_gather128(const float* __restrict__ h,
                                                   float* __restrict__ agg) {
    int v = blockIdx.x;
    int t = threadIdx.x;
    int b = g_rowptr[v], e = g_rowptr[v + 1];
    float s = g_dis[v]; s *= s;
    float acc = s * h[(size_t)v * 128 + t];
    for (int j = b; j < e; j++)
        acc += g_nrm[j] * h[(size_t)g_src[j] * 128 + t];
    agg[(size_t)v * 128 + t] = acc;
}

// ---------------- GCN GEMM + bias + ReLU + LayerNorm ----------------
__global__ void __launch_bounds__(256) k_gcn(
    const float* __restrict__ A, const float* __restrict__ W,
    const float* __restrict__ bias, const float* __restrict__ gam,
    const float* __restrict__ bet, float* __restrict__ out, int K)
{
    __shared__ float sA[16][16];
    __shared__ float sW[16][512];
    __shared__ float rsum[16][4], rsq[16][4];
    int t = threadIdx.x;
    int tx = t & 127, ty = t >> 7;
    int row0 = blockIdx.x * 16;
    unsigned long long a64[8][2];
#pragma unroll
    for (int j = 0; j < 8; j++) { a64[j][0] = 0ull; a64[j][1] = 0ull; }

    for (int k0 = 0; k0 < K; k0 += 16) {
        sA[t >> 4][t & 15] = A[(row0 + (t >> 4)) * K + k0 + (t & 15)];
#pragma unroll
        for (int i = 0; i < 8; i++) {
            int idx = t + i * 256;
            int kk = idx >> 7, c4 = idx & 127;
            *(float4*)&sW[kk][c4 * 4] = *(const float4*)&W[(k0 + kk) * 512 + c4 * 4];
        }
        __syncthreads();
#pragma unroll
        for (int kk = 0; kk < 16; kk++) {
            ulonglong2 w2 = *(ulonglong2*)&sW[kk][tx * 4];
#pragma unroll
            for (int j = 0; j < 8; j++) {
                unsigned long long aa = bcast2(sA[ty + j * 2][kk]);
                FMA2(a64[j][0], aa, w2.x);
                FMA2(a64[j][1], aa, w2.y);
            }
        }
        __syncthreads();
    }

    float acc[8][4];
#pragma unroll
    for (int j = 0; j < 8; j++) {
        unpack2(a64[j][0], acc[j][0], acc[j][1]);
        unpack2(a64[j][1], acc[j][2], acc[j][3]);
    }

    float4 b4 = *(const float4*)&bias[tx * 4];
    int lane = t & 31, quarter = (t >> 5) & 3;
#pragma unroll
    for (int j = 0; j < 8; j++) {
        acc[j][0] = fmaxf(acc[j][0] + b4.x, 0.f);
        acc[j][1] = fmaxf(acc[j][1] + b4.y, 0.f);
        acc[j][2] = fmaxf(acc[j][2] + b4.z, 0.f);
        acc[j][3] = fmaxf(acc[j][3] + b4.w, 0.f);
        int r = ty + j * 2;
        float s = acc[j][0] + acc[j][1] + acc[j][2] + acc[j][3];
        float q = acc[j][0]*acc[j][0] + acc[j][1]*acc[j][1]
                + acc[j][2]*acc[j][2] + acc[j][3]*acc[j][3];
        s = warp_sum(s); q = warp_sum(q);
        if (lane == 0) { rsum[r][quarter] = s; rsq[r][quarter] = q; }
    }
    __syncthreads();
    float4 g4  = *(const float4*)&gam[tx * 4];
    float4 be4 = *(const float4*)&bet[tx * 4];
#pragma unroll
    for (int j = 0; j < 8; j++) {
        int r = ty + j * 2;
        float s = rsum[r][0] + rsum[r][1] + rsum[r][2] + rsum[r][3];
        float q = rsq[r][0]  + rsq[r][1]  + rsq[r][2]  + rsq[r][3];
        float mu  = s * (1.f / 512.f);
        float var = q * (1.f / 512.f) - mu * mu;
        float rs  = rsqrtf(var + EPS);
        float4 o;
        o.x = (acc[j][0] - mu) * rs * g4.x + be4.x;
        o.y = (acc[j][1] - mu) * rs * g4.y + be4.y;
        o.z = (acc[j][2] - mu) * rs * g4.z + be4.z;
        o.w = (acc[j][3] - mu) * rs * g4.w + be4.w;
        *(float4*)&out[(row0 + r) * 512 + tx * 4] = o;
    }
}

// ---------------- tiled GEMM: C[N_PAD,1024] = Ain[N_PAD,512] @ W[512,1024] ----------------
__global__ void __launch_bounds__(256) k_gemm64(
    const float* __restrict__ Ain, const float* __restrict__ W, float* __restrict__ C)
{
    __shared__ float sA[64][20];
    __shared__ float sB[16][64];
    int t = threadIdx.x;
    int tx = t & 15, ty = t >> 4;
    int c0 = blockIdx.x * 64, r0 = blockIdx.y * 64;
    unsigned long long a64[4][2];
#pragma unroll
    for (int i = 0; i < 4; i++) { a64[i][0] = 0ull; a64[i][1] = 0ull; }

    for (int k0 = 0; k0 < 512; k0 += 16) {
        {
            int r = t >> 2, q = t & 3;
            *(float4*)&sA[r][q * 4] = *(const float4*)&Ain[(r0 + r) * 512 + k0 + q * 4];
        }
        {
            int kk = t >> 4, c4 = t & 15;
            *(float4*)&sB[kk][c4 * 4] = *(const float4*)&W[(size_t)(k0 + kk) * 1024 + c0 + c4 * 4];
        }
        __syncthreads();
#pragma unroll
        for (int kk = 0; kk < 16; kk++) {
            ulonglong2 b2 = *(ulonglong2*)&sB[kk][tx * 4];
#pragma unroll
            for (int i = 0; i < 4; i++) {
                unsigned long long aa = bcast2(sA[ty * 4 + i][kk]);
                FMA2(a64[i][0], aa, b2.x);
                FMA2(a64[i][1], aa, b2.y);
            }
        }
        __syncthreads();
    }
#pragma unroll
    for (int i = 0; i < 4; i++) {
        float4 o;
        unpack2(a64[i][0], o.x, o.y);
        unpack2(a64[i][1], o.z, o.w);
        *(float4*)&C[(size_t)(r0 + ty * 4 + i) * 1024 + c0 + tx * 4] = o;
    }
}

// ---------------- fused edge MLP (stages 1+2, tensor cores) ----------------
// R13 structure, PLUS: W double-buffered via cp.async (zero register cost),
// issued one chunk ahead so the W L2 read hides behind Z staging + prev mma.
// Z stays single-buffered exactly as in R13 (no cross-iteration registers).
// dynamic smem words: Wbuf 2*16*520, Zbuf 64*20, partials 3*256, idx 2*64, stats 2*64
#define WSTR   520
#define WBUFW  (16 * WSTR)
#define ZBUFW  (64 * 20)
#define E12_SMEM_WORDS (2*WBUFW + ZBUFW + 3*256 + 2*64 + 2*64)
#define E12_SMEM_BYTES (E12_SMEM_WORDS * 4)

__global__ void __launch_bounds__(512, 1) k_edge12(
    const void* __restrict__ ei,
    const float* __restrict__ mb0, const float* __restrict__ mg0,
    const float* __restrict__ mbt0,
    const float* __restrict__ mb1,
    const float* __restrict__ g, const float* __restrict__ bt,
    const float* __restrict__ mw2, const float* __restrict__ mb2,
    float* __restrict__ out)
{
    extern __shared__ unsigned dyn[];
    unsigned* Wbuf = dyn;                    // [2][16][520]
    unsigned* Zbuf = dyn + 2 * WBUFW;        // [64][20]
    float* ps  = (float*)(Zbuf + ZBUFW);     // [64][4]
    float* pq  = ps + 256;
    float* pd  = pq + 256;
    int*   sS  = (int*)(pd + 256);
    int*   sD  = sS + 64;
    float* sMu = (float*)(sD + 64);
    float* sRs = sMu + 64;

    int t = threadIdx.x;
    int w = t >> 5, lane = t & 31;
    int gq = lane >> 2, tig = lane & 3;
    int row_half = w & 3, s = w >> 2;
    int lr0 = row_half * 16;
    int c0s = s * 128;
    int e0 = blockIdx.x * 64;

    if (t < 64) {
        sS[t] = eidx(ei, e0 + t);
        sD[t] = eidx(ei, N_EDGES + e0 + t);
    }
    // prefetch W chunk 0 while pass-1 runs (indices not needed for W)
#pragma unroll
    for (int i = 0; i < 4; i++) {
        int vi = t + i * 512;
        int kk = vi >> 7, c4 = vi & 127;
        cpasync16(&Wbuf[kk * WSTR + c4 * 4], &g_W1t[(size_t)kk * 512 + c4 * 4]);
    }
    CP_COMMIT();
    __syncthreads();

    // ---- pass 1: LN stats (each warp: 4 rows) ----
#pragma unroll
    for (int rr = 0; rr < 4; rr++) {
        int r = w * 4 + rr;
        const float* pa = &g_A[(size_t)sS[r] * 1024];
        const float* pb = &g_B[(size_t)sD[r] * 1024];
        float sm = 0.f, sq = 0.f;
#pragma unroll
        for (int i = 0; i < 8; i++) {
            int c = i * 128 + lane * 4;
            float4 a = *(const float4*)&pa[c];
            float4 b = *(const float4*)&pb[c];
            float4 m = *(const float4*)&mb0[c];
            float v0 = a.x + b.x + m.x, v1 = a.y + b.y + m.y;
            float v2 = a.z + b.z + m.z, v3 = a.w + b.w + m.w;
            sm += v0 + v1 + v2 + v3;
            sq += v0*v0 + v1*v1 + v2*v2 + v3*v3;
        }
        sm = warp_sum(sm); sq = warp_sum(sq);
        if (lane == 0) {
            float mu = sm * (1.f / 1024.f);
            float var = sq * (1.f / 1024.f) - mu * mu;
            sMu[r] = mu;
            sRs[r] = rsqrtf(var + EPS);
        }
    }
    __syncthreads();

    float acc[16][4];
#pragma unroll
    for (int i = 0; i < 16; i++) { acc[i][0]=0.f; acc[i][1]=0.f; acc[i][2]=0.f; acc[i][3]=0.f; }

    int zrow = t >> 3, zkk = (t & 7) * 2;
    const float* zpa = &g_A[(size_t)sS[zrow] * 1024];
    const float* zpb = &g_B[(size_t)sD[zrow] * 1024];
    float zmu = sMu[zrow], zrs = sRs[zrow];

    // ---- main k-loop: W double-buffered one chunk ahead; Z single-buffered ----
    for (int k0 = 0; k0 < 1024; k0 += 16) {
        int it  = k0 >> 4;
        int cur = it & 1, nxt = cur ^ 1;
        bool hn = (k0 + 16 < 1024);
        // issue next W chunk first so it overlaps Z staging + this iter's mma
        if (hn) {
#pragma unroll
            for (int i = 0; i < 4; i++) {
                int vi = t + i * 512;
                int kk = vi >> 7, c4 = vi & 127;
                cpasync16(&Wbuf[nxt * WBUFW + kk * WSTR + c4 * 4],
                          &g_W1t[(size_t)(k0 + 16 + kk) * 512 + c4 * 4]);
            }
            CP_COMMIT();
        }
        // stage Z chunk: recompute relu(LN(A[s]+B[t]+mb0)) inline (same as R13)
        {
            int c = k0 + zkk;
            float2 a2 = *(const float2*)&zpa[c];
            float2 b2 = *(const float2*)&zpb[c];
            float2 m2 = *(const float2*)&mb0[c];
            float2 gg = *(const float2*)&mg0[c];
            float2 bb = *(const float2*)&mbt0[c];
            float z0 = fmaxf((a2.x + b2.x + m2.x - zmu) * zrs * gg.x + bb.x, 0.f);
            float z1 = fmaxf((a2.y + b2.y + m2.y - zmu) * zrs * gg.y + bb.y, 0.f);
            Zbuf[zrow * 20 + zkk]     = tf32cvt(z0);
            Zbuf[zrow * 20 + zkk + 1] = tf32cvt(z1);
        }
        // wait: current W chunk complete (next one may stay in flight)
        if (hn) { CP_WAIT1(); } else { CP_WAIT0(); }
        __syncthreads();
        const unsigned* Wc = &Wbuf[cur * WBUFW];
#pragma unroll
        for (int k8 = 0; k8 < 16; k8 += 8) {
            unsigned a0 = Zbuf[(lr0 + gq     ) * 20 + k8 + tig];
            unsigned a1 = Zbuf[(lr0 + gq +  8) * 20 + k8 + tig];
            unsigned a2 = Zbuf[(lr0 + gq     ) * 20 + k8 + tig + 4];
            unsigned a3 = Zbuf[(lr0 + gq +  8) * 20 + k8 + tig + 4];
#pragma unroll
            for (int i = 0; i < 16; i++) {
                unsigned b0 = Wc[(k8 + tig    ) * WSTR + c0s + i * 8 + gq];
                unsigned b1 = Wc[(k8 + tig + 4) * WSTR + c0s + i * 8 + gq];
                mma_tf32(acc[i], a0, a1, a2, a3, b0, b1);
            }
        }
        __syncthreads();   // Zbuf reused next iter; Wbuf[nxt] written next iter
    }

    int rA = lr0 + gq, rB = rA + 8;

    float sA = 0.f, qA = 0.f, sB = 0.f, qB = 0.f;
#pragma unroll
    for (int i = 0; i < 16; i++) {
        int col = c0s + i * 8 + 2 * tig;
        float2 b2 = *(const float2*)&mb1[col];
        acc[i][0] += b2.x; acc[i][1] += b2.y;
        acc[i][2] += b2.x; acc[i][3] += b2.y;
        sA += acc[i][0] + acc[i][1];
        qA += acc[i][0]*acc[i][0] + acc[i][1]*acc[i][1];
        sB += acc[i][2] + acc[i][3];
        qB += acc[i][2]*acc[i][2] + acc[i][3]*acc[i][3];
    }
#pragma unroll
    for (int o = 1; o <= 2; o <<= 1) {
        sA += __shfl_xor_sync(0xffffffffu, sA, o);
        qA += __shfl_xor_sync(0xffffffffu, qA, o);
        sB += __shfl_xor_sync(0xffffffffu, sB, o);
        qB += __shfl_xor_sync(0xffffffffu, qB, o);
    }
    if (tig == 0) { ps[rA*4+s] = sA; pq[rA*4+s] = qA; ps[rB*4+s] = sB; pq[rB*4+s] = qB; }
    __syncthreads();

    float SA = ps[rA*4+0] + ps[rA*4+1] + ps[rA*4+2] + ps[rA*4+3];
    float QA = pq[rA*4+0] + pq[rA*4+1] + pq[rA*4+2] + pq[rA*4+3];
    float SB = ps[rB*4+0] + ps[rB*4+1] + ps[rB*4+2] + ps[rB*4+3];
    float QB = pq[rB*4+0] + pq[rB*4+1] + pq[rB*4+2] + pq[rB*4+3];
    float muA = SA * (1.f / 512.f);
    float rsA = rsqrtf(QA * (1.f / 512.f) - muA * muA + EPS);
    float muB = SB * (1.f / 512.f);
    float rsB = rsqrtf(QB * (1.f / 512.f) - muB * muB + EPS);

    float dA = 0.f, dB = 0.f;
#pragma unroll
    for (int i = 0; i < 16; i++) {
        int col = c0s + i * 8 + 2 * tig;
        float2 gm = *(const float2*)&g[col];
        float2 bb = *(const float2*)&bt[col];
        float2 w2 = *(const float2*)&mw2[col];
        dA += fmaxf((acc[i][0] - muA) * rsA * gm.x + bb.x, 0.f) * w2.x
            + fmaxf((acc[i][1] - muA) * rsA * gm.y + bb.y, 0.f) * w2.y;
        dB += fmaxf((acc[i][2] - muB) * rsB * gm.x + bb.x, 0.f) * w2.x
            + fmaxf((acc[i][3] - muB) * rsB * gm.y + bb.y, 0.f) * w2.y;
    }
#pragma unroll
    for (int o = 1; o <= 2; o <<= 1) {
        dA += __shfl_xor_sync(0xffffffffu, dA, o);
        dB += __shfl_xor_sync(0xffffffffu, dB, o);
    }
    if (tig == 0) { pd[rA*4+s] = dA; pd[rB*4+s] = dB; }
    __syncthreads();

    if (t < 64)
        out[e0 + t] = pd[t*4+0] + pd[t*4+1] + pd[t*4+2] + pd[t*4+3] + mb2[0];
}

// ---------------- launch ----------------
extern "C" void kernel_launch(void* const* d_in, const int* in_sizes, int n_in,
                              void* d_out, int out_size)
{
    const float* x    = (const float*)d_in[0];
    const void*  ei   = d_in[1];
    const float* w0   = (const float*)d_in[2];
    const float* b0   = (const float*)d_in[3];
    const float* ws   = (const float*)d_in[4];
    const float* bs   = (const float*)d_in[5];
    const float* lng  = (const float*)d_in[6];
    const float* lnb  = (const float*)d_in[7];
    const float* mw0  = (const float*)d_in[8];
    const float* mb0  = (const float*)d_in[9];
    const float* mg0  = (const float*)d_in[10];
    const float* mbt0 = (const float*)d_in[11];
    const float* mw1  = (const float*)d_in[12];
    const float* mb1  = (const float*)d_in[13];
    const float* mg1  = (const float*)d_in[14];
    const float* mbt1 = (const float*)d_in[15];
    const float* mw2  = (const float*)d_in[16];
    const float* mb2  = (const float*)d_in[17];
    float* out = (float*)d_out;

    float *p_agg, *p_h, *p_A, *p_B;
    cudaGetSymbolAddress((void**)&p_agg, g_agg);
    cudaGetSymbolAddress((void**)&p_h,   g_h);
    cudaGetSymbolAddress((void**)&p_A,   g_A);
    cudaGetSymbolAddress((void**)&p_B,   g_B);

    cudaFuncSetAttribute(k_edge12, cudaFuncAttributeMaxDynamicSharedMemorySize,
                         E12_SMEM_BYTES);

    // dtype detect + CSR build + W1 tf32 pre-convert
    k_detect<<<1, 32>>>((const int*)ei);
    k_cnt_zero<<<(N_NODES + 255) / 256, 256>>>();
    k_cnt_acc <<<(N_EDGES + 255) / 256, 256>>>(ei);
    k_scan<<<1, SCAN_T>>>();
    k_fill<<<(N_EDGES + 255) / 256, 256>>>(ei);
    k_w1cvt<<<512, 256>>>(mw1);

    // layer 0 (aggregate in 128-dim input space, then GEMM 128->512)
    k_gather128<<<N_NODES, 128>>>(x, p_agg);
    k_gcn<<<N_NODES / 16, 256>>>(p_agg, w0, b0, lng, lnb, p_h, 128);

    // layers 1..3
    for (int i = 1; i < 4; i++) {
        k_gather512<<<N_NODES, 128>>>(p_h, p_agg);
        k_gcn<<<N_NODES / 16, 256>>>(p_agg, ws + (size_t)(i - 1) * 512 * 512,
                                     bs + (i - 1) * 512, lng + i * 512, lnb + i * 512,
                                     p_h, 512);
    }

    // edge MLP first layer factored per-node: A = h @ mw0[:512], B = h @ mw0[512:]
    dim3 gAB(16, N_PAD / 64);
    k_gemm64<<<gAB, 256>>>(p_h, mw0, p_A);
    k_gemm64<<<gAB, 256>>>(p_h, mw0 + (size_t)512 * 1024, p_B);

    // fused: relu(LN(A[s]+B[t]+mb0)) @ mw1 -> LN -> relu -> dot(mw2) + mb2
    k_edge12<<<N_EDGES / 64, 512, E12_SMEM_BYTES>>>(ei, mb0, mg0, mbt0,
                                                    mb1, mg1, mbt1, mw2, mb2, out);
}

// round 17
// speedup vs baseline: 1.9350x; 1.2575x over previous
#include <cuda_runtime.h>

#define N_NODES 10000
#define N_PAD   10048
#define N_EDGES 160000
#define HID     512
#define EPS     1e-5f

// ---------------- scratch (static __device__, allowed) ----------------
__device__ float g_dis[N_NODES];
__device__ int   g_cnt[N_NODES];
__device__ int   g_rowptr[N_NODES + 1];
__device__ int   g_cur[N_NODES];
__device__ int   g_src[N_EDGES];
__device__ float g_nrm[N_EDGES];
__device__ float g_agg[N_PAD * HID];
__device__ float g_h  [N_PAD * HID];
__device__ float g_A  [N_PAD * 1024];
__device__ float g_B  [N_PAD * 1024];
__device__ unsigned g_W1t[1024 * 512];     // mw1 tf32
__device__ unsigned g_W0t[1024 * 1024];    // mw0 tf32
__device__ unsigned g_Wg0[128 * 512];      // w0 tf32
__device__ unsigned g_Wgs[3 * 512 * 512];  // ws tf32
__device__ int   g_is64;

__device__ __forceinline__ float warp_sum(float v) {
#pragma unroll
    for (int o = 16; o > 0; o >>= 1) v += __shfl_xor_sync(0xffffffffu, v, o);
    return v;
}

// ---- tf32 helpers ----
__device__ __forceinline__ unsigned tf32cvt(float f) {
    unsigned u; asm("cvt.rna.tf32.f32 %0, %1;" : "=r"(u) : "f"(f)); return u;
}
__device__ __forceinline__ void mma_tf32(float* c,
    unsigned a0, unsigned a1, unsigned a2, unsigned a3,
    unsigned b0, unsigned b1)
{
    asm volatile(
        "mma.sync.aligned.m16n8k8.row.col.f32.tf32.tf32.f32 "
        "{%0,%1,%2,%3}, {%4,%5,%6,%7}, {%8,%9}, {%0,%1,%2,%3};"
        : "+f"(c[0]), "+f"(c[1]), "+f"(c[2]), "+f"(c[3])
        : "r"(a0), "r"(a1), "r"(a2), "r"(a3), "r"(b0), "r"(b1));
}

// ---- cp.async helpers ----
__device__ __forceinline__ void cpasync16(void* smem_dst, const void* gsrc) {
    unsigned saddr = (unsigned)__cvta_generic_to_shared(smem_dst);
    asm volatile("cp.async.cg.shared.global [%0], [%1], 16;"
                 :: "r"(saddr), "l"(gsrc));
}
#define CP_COMMIT() asm volatile("cp.async.commit_group;" ::: "memory")
#define CP_WAIT0()  asm volatile("cp.async.wait_group 0;" ::: "memory")
#define CP_WAIT1()  asm volatile("cp.async.wait_group 1;" ::: "memory")

// edge_index may be int32 (JAX default) or int64; g_is64 selects.
__device__ __forceinline__ int eidx(const void* __restrict__ ei, int pos) {
    return g_is64 ? (int)((const long long*)ei)[pos] : ((const int*)ei)[pos];
}

// ---------------- dtype detection ----------------
__global__ void k_detect(const int* __restrict__ ei32) {
    if (threadIdx.x == 0) {
        int all0 = 1;
        for (int i = 0; i < 1000; i++)
            if (ei32[2 * i + 1] != 0) { all0 = 0; break; }
        g_is64 = all0;
    }
}

// ---------------- generic fp32 -> tf32 convert ----------------
__global__ void k_cvt(const float* __restrict__ src, unsigned* __restrict__ dst) {
    int i = (blockIdx.x * blockDim.x + threadIdx.x) * 4;
    float4 w4 = *(const float4*)&src[i];
    uint4 o;
    o.x = tf32cvt(w4.x); o.y = tf32cvt(w4.y);
    o.z = tf32cvt(w4.z); o.w = tf32cvt(w4.w);
    *(uint4*)&dst[i] = o;
}

// ---------------- CSR build ----------------
__global__ void k_cnt_zero() {
    int i = blockIdx.x * blockDim.x + threadIdx.x;
    if (i < N_NODES) g_cnt[i] = 0;
}
__global__ void k_cnt_acc(const void* __restrict__ ei) {
    int e = blockIdx.x * blockDim.x + threadIdx.x;
    if (e < N_EDGES) atomicAdd(&g_cnt[eidx(ei, N_EDGES + e)], 1);
}
#define SCAN_T 1024
#define SCAN_C 10
__global__ void __launch_bounds__(SCAN_T) k_scan() {
    __shared__ int part[SCAN_T];
    int t = threadIdx.x;
    int base = t * SCAN_C;
    int loc[SCAN_C];
    int s = 0;
#pragma unroll
    for (int i = 0; i < SCAN_C; i++) {
        int n = base + i;
        int c = (n < N_NODES) ? g_cnt[n] : 0;
        loc[i] = s; s += c;
    }
    part[t] = s;
    __syncthreads();
    for (int off = 1; off < SCAN_T; off <<= 1) {
        int v = (t >= off) ? part[t - off] : 0;
        __syncthreads();
        part[t] += v;
        __syncthreads();
    }
    int pre = (t > 0) ? part[t - 1] : 0;
#pragma unroll
    for (int i = 0; i < SCAN_C; i++) {
        int n = base + i;
        if (n < N_NODES) {
            int p = pre + loc[i];
            g_rowptr[n] = p;
            g_cur[n]    = p;
            g_dis[n]    = rsqrtf((float)g_cnt[n] + 1.0f);  // +1 self-loop
        }
    }
    if (t == SCAN_T - 1) g_rowptr[N_NODES] = part[t];
}
__global__ void k_fill(const void* __restrict__ ei) {
    int e = blockIdx.x * blockDim.x + threadIdx.x;
    if (e >= N_EDGES) return;
    int r = eidx(ei, e);
    int c = eidx(ei, N_EDGES + e);
    int p = atomicAdd(&g_cur[c], 1);
    g_src[p] = r;
    g_nrm[p] = g_dis[r] * g_dis[c];
}

// ---------------- aggregation: pure gather via CSR (no atomics) ----------------
__global__ void __launch_bounds__(128) k_gather512(const float* __restrict__ h,
                                                   float* __restrict__ agg) {
    int v = blockIdx.x;
    int t = threadIdx.x;
    int b = g_rowptr[v], e = g_rowptr[v + 1];
    float s = g_dis[v]; s *= s;
    float4 hv = *(const float4*)&h[(size_t)v * 512 + t * 4];
    float4 acc;
    acc.x = s * hv.x; acc.y = s * hv.y; acc.z = s * hv.z; acc.w = s * hv.w;
    for (int j = b; j < e; j++) {
        int   src = g_src[j];
        float nr  = g_nrm[j];
        float4 x = *(const float4*)&h[(size_t)src * 512 + t * 4];
        acc.x += nr * x.x; acc.y += nr * x.y;
        acc.z += nr * x.z; acc.w += nr * x.w;
    }
    *(float4*)&agg[(size_t)v * 512 + t * 4] = acc;
}
__global__ void __launch_bounds__(128) k_gather128(const float* __restrict__ h,
                                                   float* __restrict__ agg) {
    int v = blockIdx.x;
    int t = threadIdx.x;
    int b = g_rowptr[v], e = g_rowptr[v + 1];
    float s = g_dis[v]; s *= s;
    float acc = s * h[(size_t)v * 128 + t];
    for (int j = b; j < e; j++)
        acc += g_nrm[j] * h[(size_t)g_src[j] * 128 + t];
    agg[(size_t)v * 128 + t] = acc;
}

// ================= shared tf32 MMA tile geometry =================
// 64 rows x 512 cols per block, 512 threads = 16 warps (4 row-strips x 4 col-strips)
// K in chunks of 16; W double-buffered via cp.async; A staged fp32->tf32.
#define WSTR   520
#define WBUFW  (16 * WSTR)
#define ZBUFW  (64 * 20)
#define GT_SMEM_WORDS (2*WBUFW + ZBUFW + 2*256)
#define GT_SMEM_BYTES (GT_SMEM_WORDS * 4)

// ---------------- GCN layer: out = LN(relu(A @ W + bias)) (tensor cores) ----------------
__global__ void __launch_bounds__(512, 1) k_gcn_t(
    const float* __restrict__ A, const unsigned* __restrict__ Wt,
    const float* __restrict__ bias, const float* __restrict__ gam,
    const float* __restrict__ bet, float* __restrict__ out, int K)
{
    extern __shared__ unsigned dyn[];
    unsigned* Wbuf = dyn;                 // [2][16][520]
    unsigned* Zbuf = dyn + 2 * WBUFW;     // [64][20]
    float* ps = (float*)(Zbuf + ZBUFW);   // [64][4]
    float* pq = ps + 256;

    int t = threadIdx.x;
    int w = t >> 5, lane = t & 31;
    int gq = lane >> 2, tig = lane & 3;
    int row_half = w & 3, s = w >> 2;
    int lr0 = row_half * 16;
    int c0s = s * 128;
    int row0 = blockIdx.x * 64;

    // prefetch W chunk 0
#pragma unroll
    for (int i = 0; i < 4; i++) {
        int vi = t + i * 512;
        int kk = vi >> 7, c4 = vi & 127;
        cpasync16(&Wbuf[kk * WSTR + c4 * 4], &Wt[(size_t)kk * 512 + c4 * 4]);
    }
    CP_COMMIT();

    float acc[16][4];
#pragma unroll
    for (int i = 0; i < 16; i++) { acc[i][0]=0.f; acc[i][1]=0.f; acc[i][2]=0.f; acc[i][3]=0.f; }

    int zrow = t >> 3, zkk = (t & 7) * 2;
    const float* zp = &A[(size_t)(row0 + zrow) * K];

    for (int k0 = 0; k0 < K; k0 += 16) {
        int it  = k0 >> 4;
        int cur = it & 1, nxt = cur ^ 1;
        bool hn = (k0 + 16 < K);
        if (hn) {
#pragma unroll
            for (int i = 0; i < 4; i++) {
                int vi = t + i * 512;
                int kk = vi >> 7, c4 = vi & 127;
                cpasync16(&Wbuf[nxt * WBUFW + kk * WSTR + c4 * 4],
                          &Wt[(size_t)(k0 + 16 + kk) * 512 + c4 * 4]);
            }
            CP_COMMIT();
        }
        {
            float2 a2 = *(const float2*)&zp[k0 + zkk];
            Zbuf[zrow * 20 + zkk]     = tf32cvt(a2.x);
            Zbuf[zrow * 20 + zkk + 1] = tf32cvt(a2.y);
        }
        if (hn) { CP_WAIT1(); } else { CP_WAIT0(); }
        __syncthreads();
        const unsigned* Wc = &Wbuf[cur * WBUFW];
#pragma unroll
        for (int k8 = 0; k8 < 16; k8 += 8) {
            unsigned a0 = Zbuf[(lr0 + gq     ) * 20 + k8 + tig];
            unsigned a1 = Zbuf[(lr0 + gq +  8) * 20 + k8 + tig];
            unsigned a2 = Zbuf[(lr0 + gq     ) * 20 + k8 + tig + 4];
            unsigned a3 = Zbuf[(lr0 + gq +  8) * 20 + k8 + tig + 4];
#pragma unroll
            for (int i = 0; i < 16; i++) {
                unsigned b0 = Wc[(k8 + tig    ) * WSTR + c0s + i * 8 + gq];
                unsigned b1 = Wc[(k8 + tig + 4) * WSTR + c0s + i * 8 + gq];
                mma_tf32(acc[i], a0, a1, a2, a3, b0, b1);
            }
        }
        __syncthreads();
    }

    int rA = lr0 + gq, rB = rA + 8;

    // bias + relu + partial stats
    float sA = 0.f, qA = 0.f, sB = 0.f, qB = 0.f;
#pragma unroll
    for (int i = 0; i < 16; i++) {
        int col = c0s + i * 8 + 2 * tig;
        float2 b2 = *(const float2*)&bias[col];
        acc[i][0] = fmaxf(acc[i][0] + b2.x, 0.f);
        acc[i][1] = fmaxf(acc[i][1] + b2.y, 0.f);
        acc[i][2] = fmaxf(acc[i][2] + b2.x, 0.f);
        acc[i][3] = fmaxf(acc[i][3] + b2.y, 0.f);
        sA += acc[i][0] + acc[i][1];
        qA += acc[i][0]*acc[i][0] + acc[i][1]*acc[i][1];
        sB += acc[i][2] + acc[i][3];
        qB += acc[i][2]*acc[i][2] + acc[i][3]*acc[i][3];
    }
#pragma unroll
    for (int o = 1; o <= 2; o <<= 1) {
        sA += __shfl_xor_sync(0xffffffffu, sA, o);
        qA += __shfl_xor_sync(0xffffffffu, qA, o);
        sB += __shfl_xor_sync(0xffffffffu, sB, o);
        qB += __shfl_xor_sync(0xffffffffu, qB, o);
    }
    if (tig == 0) { ps[rA*4+s] = sA; pq[rA*4+s] = qA; ps[rB*4+s] = sB; pq[rB*4+s] = qB; }
    __syncthreads();

    float SA = ps[rA*4+0] + ps[rA*4+1] + ps[rA*4+2] + ps[rA*4+3];
    float QA = pq[rA*4+0] + pq[rA*4+1] + pq[rA*4+2] + pq[rA*4+3];
    float SB = ps[rB*4+0] + ps[rB*4+1] + ps[rB*4+2] + ps[rB*4+3];
    float QB = pq[rB*4+0] + pq[rB*4+1] + pq[rB*4+2] + pq[rB*4+3];
    float muA = SA * (1.f / 512.f);
    float rsA = rsqrtf(QA * (1.f / 512.f) - muA * muA + EPS);
    float muB = SB * (1.f / 512.f);
    float rsB = rsqrtf(QB * (1.f / 512.f) - muB * muB + EPS);

#pragma unroll
    for (int i = 0; i < 16; i++) {
        int col = c0s + i * 8 + 2 * tig;
        float2 gm = *(const float2*)&gam[col];
        float2 bb = *(const float2*)&bet[col];
        float2 oA, oB;
        oA.x = (acc[i][0] - muA) * rsA * gm.x + bb.x;
        oA.y = (acc[i][1] - muA) * rsA * gm.y + bb.y;
        oB.x = (acc[i][2] - muB) * rsB * gm.x + bb.x;
        oB.y = (acc[i][3] - muB) * rsB * gm.y + bb.y;
        *(float2*)&out[(size_t)(row0 + rA) * 512 + col] = oA;
        *(float2*)&out[(size_t)(row0 + rB) * 512 + col] = oB;
    }
}

// ---------------- A/B GEMM: g_A / g_B = h @ mw0 halves (tensor cores) ----------------
// grid (157, 4): q=0,1 -> A cols q*512 (mw0 rows 0..511); q=2,3 -> B cols (q-2)*512 (mw0 rows 512..1023)
__global__ void __launch_bounds__(512, 1) k_ab_t(const float* __restrict__ h)
{
    extern __shared__ unsigned dyn[];
    unsigned* Wbuf = dyn;
    unsigned* Zbuf = dyn + 2 * WBUFW;

    int t = threadIdx.x;
    int w = t >> 5, lane = t & 31;
    int gq = lane >> 2, tig = lane & 3;
    int row_half = w & 3, s = w >> 2;
    int lr0 = row_half * 16;
    int c0s = s * 128;
    int row0 = blockIdx.x * 64;
    int q = blockIdx.y;
    int isB = q >> 1, coff = (q & 1) * 512;
    const unsigned* Wt = g_W0t + (size_t)isB * 512 * 1024 + coff;  // ld = 1024
    float* outp = isB ? g_B : g_A;

#pragma unroll
    for (int i = 0; i < 4; i++) {
        int vi = t + i * 512;
        int kk = vi >> 7, c4 = vi & 127;
        cpasync16(&Wbuf[kk * WSTR + c4 * 4], &Wt[(size_t)kk * 1024 + c4 * 4]);
    }
    CP_COMMIT();

    float acc[16][4];
#pragma unroll
    for (int i = 0; i < 16; i++) { acc[i][0]=0.f; acc[i][1]=0.f; acc[i][2]=0.f; acc[i][3]=0.f; }

    int zrow = t >> 3, zkk = (t & 7) * 2;
    const float* zp = &h[(size_t)(row0 + zrow) * 512];

    for (int k0 = 0; k0 < 512; k0 += 16) {
        int it  = k0 >> 4;
        int cur = it & 1, nxt = cur ^ 1;
        bool hn = (k0 + 16 < 512);
        if (hn) {
#pragma unroll
            for (int i = 0; i < 4; i++) {
                int vi = t + i * 512;
                int kk = vi >> 7, c4 = vi & 127;
                cpasync16(&Wbuf[nxt * WBUFW + kk * WSTR + c4 * 4],
                          &Wt[(size_t)(k0 + 16 + kk) * 1024 + c4 * 4]);
            }
            CP_COMMIT();
        }
        {
            float2 a2 = *(const float2*)&zp[k0 + zkk];
            Zbuf[zrow * 20 + zkk]     = tf32cvt(a2.x);
            Zbuf[zrow * 20 + zkk + 1] = tf32cvt(a2.y);
        }
        if (hn) { CP_WAIT1(); } else { CP_WAIT0(); }
        __syncthreads();
        const unsigned* Wc = &Wbuf[cur * WBUFW];
#pragma unroll
        for (int k8 = 0; k8 < 16; k8 += 8) {
            unsigned a0 = Zbuf[(lr0 + gq     ) * 20 + k8 + tig];
            unsigned a1 = Zbuf[(lr0 + gq +  8) * 20 + k8 + tig];
            unsigned a2 = Zbuf[(lr0 + gq     ) * 20 + k8 + tig + 4];
            unsigned a3 = Zbuf[(lr0 + gq +  8) * 20 + k8 + tig + 4];
#pragma unroll
            for (int i = 0; i < 16; i++) {
                unsigned b0 = Wc[(k8 + tig    ) * WSTR + c0s + i * 8 + gq];
                unsigned b1 = Wc[(k8 + tig + 4) * WSTR + c0s + i * 8 + gq];
                mma_tf32(acc[i], a0, a1, a2, a3, b0, b1);
            }
        }
        __syncthreads();
    }

    int rA = lr0 + gq, rB = rA + 8;
#pragma unroll
    for (int i = 0; i < 16; i++) {
        int col = coff + c0s + i * 8 + 2 * tig;
        float2 oA, oB;
        oA.x = acc[i][0]; oA.y = acc[i][1];
        oB.x = acc[i][2]; oB.y = acc[i][3];
        *(float2*)&outp[(size_t)(row0 + rA) * 1024 + col] = oA;
        *(float2*)&outp[(size_t)(row0 + rB) * 1024 + col] = oB;
    }
}

// ---------------- fused edge MLP (stages 1+2, tensor cores) ----------------
#define E12_SMEM_WORDS (2*WBUFW + ZBUFW + 3*256 + 2*64 + 2*64)
#define E12_SMEM_BYTES (E12_SMEM_WORDS * 4)

__global__ void __launch_bounds__(512, 1) k_edge12(
    const void* __restrict__ ei,
    const float* __restrict__ mb0, const float* __restrict__ mg0,
    const float* __restrict__ mbt0,
    const float* __restrict__ mb1,
    const float* __restrict__ g, const float* __restrict__ bt,
    const float* __restrict__ mw2, const float* __restrict__ mb2,
    float* __restrict__ out)
{
    extern __shared__ unsigned dyn[];
    unsigned* Wbuf = dyn;                    // [2][16][520]
    unsigned* Zbuf = dyn + 2 * WBUFW;        // [64][20]
    float* ps  = (float*)(Zbuf + ZBUFW);     // [64][4]
    float* pq  = ps + 256;
    float* pd  = pq + 256;
    int*   sS  = (int*)(pd + 256);
    int*   sD  = sS + 64;
    float* sMu = (float*)(sD + 64);
    float* sRs = sMu + 64;

    int t = threadIdx.x;
    int w = t >> 5, lane = t & 31;
    int gq = lane >> 2, tig = lane & 3;
    int row_half = w & 3, s = w >> 2;
    int lr0 = row_half * 16;
    int c0s = s * 128;
    int e0 = blockIdx.x * 64;

    if (t < 64) {
        sS[t] = eidx(ei, e0 + t);
        sD[t] = eidx(ei, N_EDGES + e0 + t);
    }
#pragma unroll
    for (int i = 0; i < 4; i++) {
        int vi = t + i * 512;
        int kk = vi >> 7, c4 = vi & 127;
        cpasync16(&Wbuf[kk * WSTR + c4 * 4], &g_W1t[(size_t)kk * 512 + c4 * 4]);
    }
    CP_COMMIT();
    __syncthreads();

    // ---- pass 1: LN stats (each warp: 4 rows) ----
#pragma unroll
    for (int rr = 0; rr < 4; rr++) {
        int r = w * 4 + rr;
        const float* pa = &g_A[(size_t)sS[r] * 1024];
        const float* pb = &g_B[(size_t)sD[r] * 1024];
        float sm = 0.f, sq = 0.f;
#pragma unroll
        for (int i = 0; i < 8; i++) {
            int c = i * 128 + lane * 4;
            float4 a = *(const float4*)&pa[c];
            float4 b = *(const float4*)&pb[c];
            float4 m = *(const float4*)&mb0[c];
            float v0 = a.x + b.x + m.x, v1 = a.y + b.y + m.y;
            float v2 = a.z + b.z + m.z, v3 = a.w + b.w + m.w;
            sm += v0 + v1 + v2 + v3;
            sq += v0*v0 + v1*v1 + v2*v2 + v3*v3;
        }
        sm = warp_sum(sm); sq = warp_sum(sq);
        if (lane == 0) {
            float mu = sm * (1.f / 1024.f);
            float var = sq * (1.f / 1024.f) - mu * mu;
            sMu[r] = mu;
            sRs[r] = rsqrtf(var + EPS);
        }
    }
    __syncthreads();

    float acc[16][4];
#pragma unroll
    for (int i = 0; i < 16; i++) { acc[i][0]=0.f; acc[i][1]=0.f; acc[i][2]=0.f; acc[i][3]=0.f; }

    int zrow = t >> 3, zkk = (t & 7) * 2;
    const float* zpa = &g_A[(size_t)sS[zrow] * 1024];
    const float* zpb = &g_B[(size_t)sD[zrow] * 1024];
    float zmu = sMu[zrow], zrs = sRs[zrow];

    for (int k0 = 0; k0 < 1024; k0 += 16) {
        int it  = k0 >> 4;
        int cur = it & 1, nxt = cur ^ 1;
        bool hn = (k0 + 16 < 1024);
        if (hn) {
#pragma unroll
            for (int i = 0; i < 4; i++) {
                int vi = t + i * 512;
                int kk = vi >> 7, c4 = vi & 127;
                cpasync16(&Wbuf[nxt * WBUFW + kk * WSTR + c4 * 4],
                          &g_W1t[(size_t)(k0 + 16 + kk) * 512 + c4 * 4]);
            }
            CP_COMMIT();
        }
        {
            int c = k0 + zkk;
            float2 a2 = *(const float2*)&zpa[c];
            float2 b2 = *(const float2*)&zpb[c];
            float2 m2 = *(const float2*)&mb0[c];
            float2 gg = *(const float2*)&mg0[c];
            float2 bb = *(const float2*)&mbt0[c];
            float z0 = fmaxf((a2.x + b2.x + m2.x - zmu) * zrs * gg.x + bb.x, 0.f);
            float z1 = fmaxf((a2.y + b2.y + m2.y - zmu) * zrs * gg.y + bb.y, 0.f);
            Zbuf[zrow * 20 + zkk]     = tf32cvt(z0);
            Zbuf[zrow * 20 + zkk + 1] = tf32cvt(z1);
        }
        if (hn) { CP_WAIT1(); } else { CP_WAIT0(); }
        __syncthreads();
        const unsigned* Wc = &Wbuf[cur * WBUFW];
#pragma unroll
        for (int k8 = 0; k8 < 16; k8 += 8) {
            unsigned a0 = Zbuf[(lr0 + gq     ) * 20 + k8 + tig];
            unsigned a1 = Zbuf[(lr0 + gq +  8) * 20 + k8 + tig];
            unsigned a2 = Zbuf[(lr0 + gq     ) * 20 + k8 + tig + 4];
            unsigned a3 = Zbuf[(lr0 + gq +  8) * 20 + k8 + tig + 4];
#pragma unroll
            for (int i = 0; i < 16; i++) {
                unsigned b0 = Wc[(k8 + tig    ) * WSTR + c0s + i * 8 + gq];
                unsigned b1 = Wc[(k8 + tig + 4) * WSTR + c0s + i * 8 + gq];
                mma_tf32(acc[i], a0, a1, a2, a3, b0, b1);
            }
        }
        __syncthreads();
    }

    int rA = lr0 + gq, rB = rA + 8;

    float sA = 0.f, qA = 0.f, sB = 0.f, qB = 0.f;
#pragma unroll
    for (int i = 0; i < 16; i++) {
        int col = c0s + i * 8 + 2 * tig;
        float2 b2 = *(const float2*)&mb1[col];
        acc[i][0] += b2.x; acc[i][1] += b2.y;
        acc[i][2] += b2.x; acc[i][3] += b2.y;
        sA += acc[i][0] + acc[i][1];
        qA += acc[i][0]*acc[i][0] + acc[i][1]*acc[i][1];
        sB += acc[i][2] + acc[i][3];
        qB += acc[i][2]*acc[i][2] + acc[i][3]*acc[i][3];
    }
#pragma unroll
    for (int o = 1; o <= 2; o <<= 1) {
        sA += __shfl_xor_sync(0xffffffffu, sA, o);
        qA += __shfl_xor_sync(0xffffffffu, qA, o);
        sB += __shfl_xor_sync(0xffffffffu, sB, o);
        qB += __shfl_xor_sync(0xffffffffu, qB, o);
    }
    if (tig == 0) { ps[rA*4+s] = sA; pq[rA*4+s] = qA; ps[rB*4+s] = sB; pq[rB*4+s] = qB; }
    __syncthreads();

    float SA = ps[rA*4+0] + ps[rA*4+1] + ps[rA*4+2] + ps[rA*4+3];
    float QA = pq[rA*4+0] + pq[rA*4+1] + pq[rA*4+2] + pq[rA*4+3];
    float SB = ps[rB*4+0] + ps[rB*4+1] + ps[rB*4+2] + ps[rB*4+3];
    float QB = pq[rB*4+0] + pq[rB*4+1] + pq[rB*4+2] + pq[rB*4+3];
    float muA = SA * (1.f / 512.f);
    float rsA = rsqrtf(QA * (1.f / 512.f) - muA * muA + EPS);
    float muB = SB * (1.f / 512.f);
    float rsB = rsqrtf(QB * (1.f / 512.f) - muB * muB + EPS);

    float dA = 0.f, dB = 0.f;
#pragma unroll
    for (int i = 0; i < 16; i++) {
        int col = c0s + i * 8 + 2 * tig;
        float2 gm = *(const float2*)&g[col];
        float2 bb = *(const float2*)&bt[col];
        float2 w2 = *(const float2*)&mw2[col];
        dA += fmaxf((acc[i][0] - muA) * rsA * gm.x + bb.x, 0.f) * w2.x
            + fmaxf((acc[i][1] - muA) * rsA * gm.y + bb.y, 0.f) * w2.y;
        dB += fmaxf((acc[i][2] - muB) * rsB * gm.x + bb.x, 0.f) * w2.x
            + fmaxf((acc[i][3] - muB) * rsB * gm.y + bb.y, 0.f) * w2.y;
    }
#pragma unroll
    for (int o = 1; o <= 2; o <<= 1) {
        dA += __shfl_xor_sync(0xffffffffu, dA, o);
        dB += __shfl_xor_sync(0xffffffffu, dB, o);
    }
    if (tig == 0) { pd[rA*4+s] = dA; pd[rB*4+s] = dB; }
    __syncthreads();

    if (t < 64)
        out[e0 + t] = pd[t*4+0] + pd[t*4+1] + pd[t*4+2] + pd[t*4+3] + mb2[0];
}

// ---------------- launch ----------------
extern "C" void kernel_launch(void* const* d_in, const int* in_sizes, int n_in,
                              void* d_out, int out_size)
{
    const float* x    = (const float*)d_in[0];
    const void*  ei   = d_in[1];
    const float* w0   = (const float*)d_in[2];
    const float* b0   = (const float*)d_in[3];
    const float* ws   = (const float*)d_in[4];
    const float* bs   = (const float*)d_in[5];
    const float* lng  = (const float*)d_in[6];
    const float* lnb  = (const float*)d_in[7];
    const float* mw0  = (const float*)d_in[8];
    const float* mb0  = (const float*)d_in[9];
    const float* mg0  = (const float*)d_in[10];
    const float* mbt0 = (const float*)d_in[11];
    const float* mw1  = (const float*)d_in[12];
    const float* mb1  = (const float*)d_in[13];
    const float* mg1  = (const float*)d_in[14];
    const float* mbt1 = (const float*)d_in[15];
    const float* mw2  = (const float*)d_in[16];
    const float* mb2  = (const float*)d_in[17];
    float* out = (float*)d_out;

    float *p_agg, *p_h;
    cudaGetSymbolAddress((void**)&p_agg, g_agg);
    cudaGetSymbolAddress((void**)&p_h,   g_h);
    unsigned *p_W1t, *p_W0t, *p_Wg0, *p_Wgs;
    cudaGetSymbolAddress((void**)&p_W1t, g_W1t);
    cudaGetSymbolAddress((void**)&p_W0t, g_W0t);
    cudaGetSymbolAddress((void**)&p_Wg0, g_Wg0);
    cudaGetSymbolAddress((void**)&p_Wgs, g_Wgs);

    cudaFuncSetAttribute(k_edge12, cudaFuncAttributeMaxDynamicSharedMemorySize,
                         E12_SMEM_BYTES);
    cudaFuncSetAttribute(k_gcn_t, cudaFuncAttributeMaxDynamicSharedMemorySize,
                         GT_SMEM_BYTES);
    cudaFuncSetAttribute(k_ab_t, cudaFuncAttributeMaxDynamicSharedMemorySize,
                         GT_SMEM_BYTES);

    // dtype detect + CSR build + weight tf32 pre-converts
    k_detect<<<1, 32>>>((const int*)ei);
    k_cnt_zero<<<(N_NODES + 255) / 256, 256>>>();
    k_cnt_acc <<<(N_EDGES + 255) / 256, 256>>>(ei);
    k_scan<<<1, SCAN_T>>>();
    k_fill<<<(N_EDGES + 255) / 256, 256>>>(ei);
    k_cvt<<<512, 256>>>(mw1, p_W1t);                 // 1024x512
    k_cvt<<<1024, 256>>>(mw0, p_W0t);                // 1024x1024
    k_cvt<<<64, 256>>>(w0, p_Wg0);                   // 128x512
    k_cvt<<<768, 256>>>(ws, p_Wgs);                  // 3x512x512

    // layer 0 (aggregate in 128-dim input space, then GEMM 128->512)
    k_gather128<<<N_NODES, 128>>>(x, p_agg);
    k_gcn_t<<<N_PAD / 64, 512, GT_SMEM_BYTES>>>(p_agg, p_Wg0, b0, lng, lnb, p_h, 128);

    // layers 1..3
    for (int i = 1; i < 4; i++) {
        k_gather512<<<N_NODES, 128>>>(p_h, p_agg);
        k_gcn_t<<<N_PAD / 64, 512, GT_SMEM_BYTES>>>(
            p_agg, p_Wgs + (size_t)(i - 1) * 512 * 512,
            bs + (i - 1) * 512, lng + i * 512, lnb + i * 512, p_h, 512);
    }

    // edge MLP first layer factored per-node: A/B = h @ mw0 halves (tensor cores)
    dim3 gAB(N_PAD / 64, 4);
    k_ab_t<<<gAB, 512, GT_SMEM_BYTES>>>(p_h);

    // fused: relu(LN(A[s]+B[t]+mb0)) @ mw1 -> LN -> relu -> dot(mw2) + mb2
    k_edge12<<<N_EDGES / 64, 512, E12_SMEM_BYTES>>>(ei, mb0, mg0, mbt0,
                                                    mb1, mg1, mbt1, mw2, mb2, out);
}